// round 1
// baseline (speedup 1.0000x reference)
#include <cuda_runtime.h>
#include <cuda_bf16.h>

// Problem constants
#define TT 16384
#define HH 100
#define GG 400   // 4*H

// Scratch (device globals: no allocation allowed in kernel_launch)
__device__ float g_xg[TT * GG];   // precomputed input gate contributions [T, 4H]
__device__ float g_hs[TT * HH];   // hidden states [T, H]

// ---------------------------------------------------------------------------
// Packed fp32x2 FMA (Blackwell FFMA2): 2 fp32 FMAs per instruction
// ---------------------------------------------------------------------------
__device__ __forceinline__ float2 ffma2(float2 a, float2 b, float2 c) {
    float2 r;
    asm("fma.rn.f32x2 %0, %1, %2, %3;"
        : "=l"(reinterpret_cast<unsigned long long&>(r))
        : "l"(reinterpret_cast<unsigned long long&>(a)),
          "l"(reinterpret_cast<unsigned long long&>(b)),
          "l"(reinterpret_cast<unsigned long long&>(c)));
    return r;
}

__device__ __forceinline__ float sigmoid_f(float x) {
    return 1.0f / (1.0f + __expf(-x));
}

// Overflow-safe tanh via exp (accurate to ~1e-7 rel; no NaN for large |x|)
__device__ __forceinline__ float tanh_f(float x) {
    float e = __expf(-2.0f * fabsf(x));
    float r = (1.0f - e) / (1.0f + e);
    return copysignf(r, x);
}

// ---------------------------------------------------------------------------
// Kernel 1: x_gates[t][j] = b_ih[j] + b_hh[j] + sum_k x[t][k] * W_ih[j][k]
// ---------------------------------------------------------------------------
__global__ void k_xgates(const float* __restrict__ x,
                         const float* __restrict__ Wih,
                         const float* __restrict__ bih,
                         const float* __restrict__ bhh) {
    int idx = blockIdx.x * blockDim.x + threadIdx.x;
    if (idx >= TT * GG) return;
    int t = idx / GG;
    int j = idx - t * GG;
    const float* xr = x + t * 3;
    const float* wr = Wih + j * 3;
    float s = bih[j] + bhh[j];
    s += xr[0] * wr[0] + xr[1] * wr[1] + xr[2] * wr[2];
    g_xg[idx] = s;
}

// ---------------------------------------------------------------------------
// Kernel 2: sequential LSTM. One block, 13 warps (416 threads).
// Warp w, lane l: unit u = 8*w + (l&7), gate = l>>3  (gate order: i,f,g,o)
// Each thread: 100-MAC dot product (W_hh row in registers, h from SMEM
// broadcast, packed f32x2 FMA). Gates of one unit live in one warp ->
// combine via shfl. Double-buffered h -> ONE __syncthreads per step.
// ---------------------------------------------------------------------------
__global__ void __launch_bounds__(416, 1)
k_lstm_seq(const float* __restrict__ Whh) {
    __shared__ __align__(16) float sh_h[2][104];   // 104-float stride keeps 16B alignment

    const int tid  = threadIdx.x;
    const int w    = tid >> 5;
    const int l    = tid & 31;
    const int u    = w * 8 + (l & 7);
    const int gate = l >> 3;
    const bool valid = (u < HH);                    // warp 12 covers units 96..99 only
    const int row  = valid ? (gate * HH + u) : 0;   // W_hh row / x_gates column

    // Load this thread's W_hh row (100 floats, 8B-aligned) into registers
    float2 wv[50];
    {
        const float2* wr = reinterpret_cast<const float2*>(Whh + row * HH);
        #pragma unroll
        for (int i = 0; i < 50; i++) wv[i] = wr[i];
    }

    // Zero both h buffers
    for (int i = tid; i < 208; i += blockDim.x)
        (&sh_h[0][0])[i] = 0.0f;
    __syncthreads();

    float c = 0.0f;

    // 2-deep x_gates prefetch pipeline
    float xg0 = g_xg[row];
    float xg1 = g_xg[GG + row];

    for (int t = 0; t < TT; t++) {
        const float cur = xg0;
        xg0 = xg1;
        const int tn = t + 2;
        xg1 = (tn < TT) ? __ldg(&g_xg[tn * GG + row]) : 0.0f;

        const int buf = t & 1;
        const float4* hp = reinterpret_cast<const float4*>(&sh_h[buf][0]);

        // 100-MAC dot product: 25 LDS.128 (broadcast) + 50 packed FMAs
        float2 acc0 = make_float2(0.0f, 0.0f);
        float2 acc1 = make_float2(0.0f, 0.0f);
        #pragma unroll
        for (int i = 0; i < 25; i++) {
            float4 hv = hp[i];
            acc0 = ffma2(make_float2(hv.x, hv.y), wv[2 * i],     acc0);
            acc1 = ffma2(make_float2(hv.z, hv.w), wv[2 * i + 1], acc1);
        }
        float g = (acc0.x + acc0.y) + (acc1.x + acc1.y) + cur;

        // Per-gate nonlinearity
        float a = (gate == 2) ? tanh_f(g) : sigmoid_f(g);

        // Gather the 4 gate activations of this unit within the warp
        const int b = l & 7;
        float a_f = __shfl_sync(0xffffffffu, a, b + 8);
        float a_g = __shfl_sync(0xffffffffu, a, b + 16);
        float a_o = __shfl_sync(0xffffffffu, a, b + 24);

        if (gate == 0 && valid) {
            // a = i, a_f = f, a_g = g~, a_o = o
            c = a_f * c + a * a_g;
            float hn = a_o * tanh_f(c);
            sh_h[buf ^ 1][u] = hn;
            g_hs[t * HH + u] = hn;
        }
        __syncthreads();
    }
}

// ---------------------------------------------------------------------------
// Kernel 3: out[t] = sigmoid( hs[t,:] . W_lin + b_lin ).  Warp per row.
// ---------------------------------------------------------------------------
__global__ void k_proj(const float* __restrict__ Wlin,
                       const float* __restrict__ blin,
                       float* __restrict__ out) {
    int gw = (blockIdx.x * blockDim.x + threadIdx.x) >> 5;
    int l  = threadIdx.x & 31;
    if (gw >= TT) return;
    const float* hr = g_hs + gw * HH;
    float s = 0.0f;
    #pragma unroll
    for (int i = 0; i < 4; i++) {
        int k = l + 32 * i;
        if (k < HH) s += hr[k] * Wlin[k];
    }
    #pragma unroll
    for (int off = 16; off; off >>= 1)
        s += __shfl_xor_sync(0xffffffffu, s, off);
    if (l == 0) out[gw] = 1.0f / (1.0f + __expf(-(s + blin[0])));
}

// ---------------------------------------------------------------------------
// Launch
// Inputs (metadata order): input_x, W_ih, W_hh, b_ih, b_hh, W_lin, b_lin
// ---------------------------------------------------------------------------
extern "C" void kernel_launch(void* const* d_in, const int* in_sizes, int n_in,
                              void* d_out, int out_size) {
    const float* x    = (const float*)d_in[0];
    const float* Wih  = (const float*)d_in[1];
    const float* Whh  = (const float*)d_in[2];
    const float* bih  = (const float*)d_in[3];
    const float* bhh  = (const float*)d_in[4];
    const float* Wlin = (const float*)d_in[5];
    const float* blin = (const float*)d_in[6];
    float* out = (float*)d_out;

    (void)in_sizes; (void)n_in; (void)out_size;

    // 1) parallel precompute of input gate contributions
    {
        int n = TT * GG;
        k_xgates<<<(n + 255) / 256, 256>>>(x, Wih, bih, bhh);
    }
    // 2) sequential recurrence (single persistent block)
    k_lstm_seq<<<1, 416>>>(Whh);
    // 3) parallel output projection
    {
        int warps = TT;                 // one warp per timestep
        int threads = 256;              // 8 warps per block
        int blocks = (warps * 32 + threads - 1) / threads;
        k_proj<<<blocks, threads>>>(Wlin, blin, out);
    }
}